// round 12
// baseline (speedup 1.0000x reference)
#include <cuda_runtime.h>

#define Bq   64
#define NPG  501
#define NN   (Bq * NPG)        // 32064
#define HID  128
#define LMD  1024
#define NREL 42
#define EMAX 520001
#define NPAD (NN + 128)

// ---------------- packed f32x2 helpers (Blackwell FFMA2) ----------------
__device__ __forceinline__ void ffma2(unsigned long long& acc,
                                      unsigned long long a, unsigned long long b) {
    asm("fma.rn.f32x2 %0, %1, %2, %0;" : "+l"(acc) : "l"(a), "l"(b));
}
__device__ __forceinline__ unsigned long long pack2(float x) {
    unsigned long long r;
    asm("mov.b64 %0, {%1, %1};" : "=l"(r) : "f"(x));
    return r;
}
__device__ __forceinline__ float2 unpack2(unsigned long long v) {
    float2 f;
    asm("mov.b64 {%0, %1}, %2;" : "=f"(f.x), "=f"(f.y) : "l"(v));
    return f;
}

// ---------------- scratch (device globals; no allocs) ----------------
__device__ int   g_src[EMAX];
__device__ int   g_dst[EMAX];
__device__ int   g_etype[EMAX];
__device__ int   g_ctxn[Bq];
__device__ float g_ctx[Bq * HID];
__device__ float g_tdot[NREL];
__device__ float g_tmpT[Bq * HID * HID];      // [b][h][k]  (L-half 0 partial)
__device__ float g_tmpTb[Bq * HID * HID];     // L-half 1 partial
__device__ float g_x[NPAD * HID];
__device__ float g_nodes[NPAD * HID];
__device__ float g_xl[NPAD * HID];
__device__ float g_as[NPAD];
__device__ float g_ad[NPAD];
__device__ float g_loop[NN];
__device__ int   g_deg[NN];
__device__ int   g_off[NN + 1];
__device__ int   g_pos[NN];
__device__ int   g_csrc[EMAX];
__device__ float g_cae[EMAX];
// active-set pruning
__device__ int   g_isctx[NN];
__device__ int   g_m3[NN];
__device__ int   g_m2[NN];
__device__ int   g_list2[NN];
__device__ int   g_list3[NN];
__device__ int   g_cnt2;
__device__ int   g_cnt3;

// zero scratch + copy node_emb -> g_x (vectorized)
__global__ void k_init(const float* __restrict__ ne) {
    int i = blockIdx.x * blockDim.x + threadIdx.x;
    int stride = gridDim.x * blockDim.x;
    const float4* s4 = (const float4*)ne;
    float4* d4 = (float4*)g_x;
    for (int j = i; j < NN * HID / 4; j += stride) d4[j] = s4[j];
    for (int j = i; j < NN; j += stride) {
        g_deg[j] = 0; g_isctx[j] = 0; g_m3[j] = 0; g_m2[j] = 0;
    }
    if (i == 0) { g_cnt2 = 0; g_cnt3 = 0; }
}

// cvt (dtype-flexible) + degree atomics + ctx marks, all in one pass
__global__ void k_cvt(const void* __restrict__ ei, const void* __restrict__ et,
                      const void* __restrict__ ctxn, int E) {
    int i = blockIdx.x * blockDim.x + threadIdx.x;
    bool is64 = (((const int*)ctxn)[1] == 0);
    if (i < E) {
        int s, d, t;
        if (is64) {
            s = (int)((const long long*)ei)[i];
            d = (int)((const long long*)ei)[E + i];
            t = (int)((const long long*)et)[i];
        } else {
            s = ((const int*)ei)[i];
            d = ((const int*)ei)[E + i];
            t = ((const int*)et)[i];
        }
        g_src[i] = s; g_dst[i] = d; g_etype[i] = t;
        atomicAdd(&g_deg[d], 1);
    }
    if (i < Bq) {
        int n = is64 ? (int)((const long long*)ctxn)[i] : ((const int*)ctxn)[i];
        g_ctxn[i] = n;
        g_isctx[n] = 1;
        g_m3[n] = 1;
    }
}

// v_edge = W_edge@att_edge; table_dot (MUST precede k_fill)
__global__ void k_prep(const float* __restrict__ We, const float* __restrict__ ae,
                       const float* __restrict__ tab) {
    __shared__ float sv[HID];
    int t = threadIdx.x;
    float acc = 0.f;
    for (int j = 0; j < HID; j++) acc += We[t * HID + j] * ae[j];
    sv[t] = acc;
    __syncthreads();
    if (t < NREL) {
        float a2 = 0.f;
        for (int j = 0; j < HID; j++) a2 += tab[t * HID + j] * sv[j];
        g_tdot[t] = a2;
    }
}

// tmpT partials: tmpT[z][b][h][k] = sum_{l in half z} lm[b,l]*W_bil[k,l,h]
// grid (128 k, 2 h-halves of 64, 2 L-halves of 512) = 512 blocks, 128 thr.
__global__ void __launch_bounds__(128) k_tmpp(const float* __restrict__ lm,
                                              const float* __restrict__ Wb) {
    __shared__ float sW[2][32 * 64];     // 8 KB per buffer (32 l x 64 h)
    __shared__ float sA[2][64 * 36];     // 9 KB per buffer (64 b x 32 l, pad 36)
    const int k = blockIdx.x;
    const int h0 = blockIdx.y * 64;
    const int lbase = blockIdx.z * 512;
    const int t = threadIdx.x;
    const int cg = t & 7, rg = t >> 3;   // 8 col-groups, 16 row-groups
    const int b0 = rg * 4;               // 4 rows
    const int hw = cg * 8;               // 8 cols
    const float* Wk = Wb + (size_t)k * LMD * HID;

    unsigned long long acc[4][4];
#pragma unroll
    for (int i = 0; i < 4; i++)
#pragma unroll
        for (int p = 0; p < 4; p++) acc[i][p] = 0ull;

    float4 pw[4], pa[4];
#pragma unroll
    for (int j = 0; j < 4; j++) {
        int f = t + j * 128;
        pw[j] = *(const float4*)&Wk[(size_t)(lbase + (f >> 4)) * HID + h0 + (f & 15) * 4];
        pa[j] = *(const float4*)&lm[(size_t)(f >> 3) * LMD + lbase + (f & 7) * 4];
    }
#pragma unroll
    for (int j = 0; j < 4; j++) {
        int f = t + j * 128;
        *(float4*)&sW[0][(f >> 4) * 64 + (f & 15) * 4] = pw[j];
        *(float4*)&sA[0][(f >> 3) * 36 + (f & 7) * 4] = pa[j];
    }
    __syncthreads();

    for (int c = 0; c < 16; c++) {
        if (c < 15) {
            int l0 = lbase + (c + 1) * 32;
#pragma unroll
            for (int j = 0; j < 4; j++) {
                int f = t + j * 128;
                pw[j] = *(const float4*)&Wk[(size_t)(l0 + (f >> 4)) * HID + h0 + (f & 15) * 4];
                pa[j] = *(const float4*)&lm[(size_t)(f >> 3) * LMD + l0 + (f & 7) * 4];
            }
        }
        const float* cW = sW[c & 1];
        const float* cA = sA[c & 1];
#pragma unroll 8
        for (int l = 0; l < 32; l += 2) {
            float2 a[4];
#pragma unroll
            for (int i = 0; i < 4; i++)
                a[i] = *(const float2*)&cA[(b0 + i) * 36 + l];
            ulonglong2 w0a = *(const ulonglong2*)&cW[l * 64 + hw];
            ulonglong2 w0b = *(const ulonglong2*)&cW[l * 64 + hw + 4];
            ulonglong2 w1a = *(const ulonglong2*)&cW[(l + 1) * 64 + hw];
            ulonglong2 w1b = *(const ulonglong2*)&cW[(l + 1) * 64 + hw + 4];
#pragma unroll
            for (int i = 0; i < 4; i++) {
                unsigned long long p = pack2(a[i].x);
                ffma2(acc[i][0], p, w0a.x); ffma2(acc[i][1], p, w0a.y);
                ffma2(acc[i][2], p, w0b.x); ffma2(acc[i][3], p, w0b.y);
                p = pack2(a[i].y);
                ffma2(acc[i][0], p, w1a.x); ffma2(acc[i][1], p, w1a.y);
                ffma2(acc[i][2], p, w1b.x); ffma2(acc[i][3], p, w1b.y);
            }
        }
        __syncthreads();
        if (c < 15) {
            int nb = (c + 1) & 1;
#pragma unroll
            for (int j = 0; j < 4; j++) {
                int f = t + j * 128;
                *(float4*)&sW[nb][(f >> 4) * 64 + (f & 15) * 4] = pw[j];
                *(float4*)&sA[nb][(f >> 3) * 36 + (f & 7) * 4] = pa[j];
            }
        }
        __syncthreads();
    }

    float* outb = blockIdx.z ? g_tmpTb : g_tmpT;
#pragma unroll
    for (int i = 0; i < 4; i++) {
        size_t bb = (size_t)(b0 + i) * HID * HID + k;
#pragma unroll
        for (int p = 0; p < 4; p++) {
            float2 f = unpack2(acc[i][p]);
            int h = h0 + hw + 2 * p;
            outb[bb + (size_t)h * HID] = f.x;
            outb[bb + (size_t)(h + 1) * HID] = f.y;
        }
    }
}

__global__ void k_mark3(int E) {
    int i = blockIdx.x * blockDim.x + threadIdx.x;
    if (i < E && g_isctx[g_dst[i]]) g_m3[g_src[i]] = 1;
}

__global__ void k_mark2(int E) {
    int i = blockIdx.x * blockDim.x + threadIdx.x;
    if (i < E && g_m3[g_dst[i]]) g_m2[g_src[i]] = 1;
}

// single-block exclusive scan over g_deg -> g_off, g_pos
__global__ void k_scan() {
    __shared__ int sp[1024];
    int t = threadIdx.x;
    int base = t * 32;
    int loc[32];
    int s = 0;
#pragma unroll
    for (int i = 0; i < 32; i++) {
        int idx = base + i;
        int v = (idx < NN) ? g_deg[idx] : 0;
        loc[i] = s;
        s += v;
    }
    sp[t] = s;
    __syncthreads();
    for (int d = 1; d < 1024; d <<= 1) {
        int v = (t >= d) ? sp[t - d] : 0;
        __syncthreads();
        sp[t] += v;
        __syncthreads();
    }
    int chunk = (t == 0) ? 0 : sp[t - 1];
#pragma unroll
    for (int i = 0; i < 32; i++) {
        int idx = base + i;
        if (idx < NN) {
            int o = chunk + loc[i];
            g_off[idx] = o;
            g_pos[idx] = o;
        }
    }
    if (t == 1023) g_off[NN] = sp[1023];
}

__global__ void k_fill(int E) {
    int i = blockIdx.x * blockDim.x + threadIdx.x;
    if (i < E) {
        int d = g_dst[i];
        int p = atomicAdd(&g_pos[d], 1);
        g_csrc[p] = g_src[i];
        g_cae[p] = g_tdot[g_etype[i]];
    }
}

__global__ void k_compact() {
    int n = blockIdx.x * blockDim.x + threadIdx.x;
    if (n >= NN) return;
    int in3 = g_m3[n];
    int in2 = g_m2[n] | in3;
    if (in3) g_list3[atomicAdd(&g_cnt3, 1)] = n;
    if (in2) g_list2[atomicAdd(&g_cnt2, 1)] = n;
}

// self-loop attention bias = mean of incoming table_dot
__global__ void k_loopdot() {
    int w = (blockIdx.x * blockDim.x + threadIdx.x) >> 5;
    int lane = threadIdx.x & 31;
    if (w >= NN) return;
    int s = g_off[w], e = g_off[w + 1];
    float acc = 0.f;
    for (int i = s + lane; i < e; i += 32) acc += g_cae[i];
    for (int o = 16; o; o >>= 1) acc += __shfl_xor_sync(0xffffffffu, acc, o);
    if (lane == 0) {
        int d = e - s;
        g_loop[w] = d ? acc / (float)d : 0.f;
    }
}

// ctx_emb = lm @ W_lm + b_lm ; writes g_ctx and ctx rows of g_x
__global__ void __launch_bounds__(1024) k_ctx(const float* __restrict__ lm,
                                              const float* __restrict__ W,
                                              const float* __restrict__ bl) {
    __shared__ float red[1024];
    int b = blockIdx.x, t = threadIdx.x;
    int c = t & 127, lg = t >> 7;
    const float* l0 = lm + (size_t)b * LMD + lg * 128;
    const float* Wp = W + (size_t)(lg * 128) * HID + c;
    float a0 = 0.f, a1 = 0.f;
#pragma unroll 8
    for (int l = 0; l < 128; l += 2) {
        a0 += l0[l] * Wp[(size_t)l * HID];
        a1 += l0[l + 1] * Wp[(size_t)(l + 1) * HID];
    }
    red[t] = a0 + a1;
    __syncthreads();
    for (int s = 512; s >= 128; s >>= 1) {
        if (t < s) red[t] += red[t + s];
        __syncthreads();
    }
    if (t < 128) {
        float v = red[t] + bl[t];
        g_ctx[b * HID + t] = v;
        g_x[(size_t)g_ctxn[b] * HID + t] = v;
    }
}

// ===== packed f32x2 GEMM, software-pipelined A stream =====
// mode 0: A=g_x(+b*NPG*HID), B=g_tmpT[b]+g_tmpTb[b] (partials summed at stage),
//         C=g_nodes(+...), +bias
// mode 1: A=g_nodes, B=Bext(W_gat), C=g_xl, + att_src/att_dst row dots
__global__ void __launch_bounds__(256) k_gemmp(int mode, const float* __restrict__ Bext,
                                               int M, int sA,
                                               const float* __restrict__ bias,
                                               const float* __restrict__ atts,
                                               const float* __restrict__ attd) {
    __shared__ float Bs[64 * 128];      // 32 KB (K staged in 2 chunks)
    const float* A = mode ? g_nodes : g_x;
    float* C = mode ? g_xl : g_nodes;
    const float* Bm = mode ? Bext : (g_tmpT + (size_t)blockIdx.y * HID * HID);
    const float* Bm2 = mode ? nullptr : (g_tmpTb + (size_t)blockIdx.y * HID * HID);
    A += (size_t)blockIdx.y * sA;
    C += (size_t)blockIdx.y * sA;

    const int t = threadIdx.x;
    const int tc = t & 15, tr = t >> 4;
    const int r0 = blockIdx.x * 64 + tr * 4;
    const int c0 = tc * 8;

    unsigned long long acc2[4][4];
#pragma unroll
    for (int i = 0; i < 4; i++)
#pragma unroll
        for (int p = 0; p < 4; p++) acc2[i][p] = 0ull;

    // stage B chunk 0
    {
        const float4* src = (const float4*)Bm;
        float4* dst = (float4*)Bs;
        if (mode) {
#pragma unroll
            for (int j = 0; j < 8; j++) dst[t + j * 256] = src[t + j * 256];
        } else {
            const float4* src2 = (const float4*)Bm2;
#pragma unroll
            for (int j = 0; j < 8; j++) {
                float4 v = src[t + j * 256];
                float4 u = src2[t + j * 256];
                v.x += u.x; v.y += u.y; v.z += u.z; v.w += u.w;
                dst[t + j * 256] = v;
            }
        }
    }
    __syncthreads();

    // prefetch A for step 0
    float4 av[4];
#pragma unroll
    for (int i = 0; i < 4; i++)
        av[i] = *(const float4*)&A[(size_t)(r0 + i) * HID];

    for (int s = 0; s < 32; s++) {
        if (s == 16) {                      // restage B with chunk 1
            __syncthreads();
            const float4* src = (const float4*)(Bm + 64 * HID);
            float4* dst = (float4*)Bs;
            if (mode) {
#pragma unroll
                for (int j = 0; j < 8; j++) dst[t + j * 256] = src[t + j * 256];
            } else {
                const float4* src2 = (const float4*)(Bm2 + 64 * HID);
#pragma unroll
                for (int j = 0; j < 8; j++) {
                    float4 v = src[t + j * 256];
                    float4 u = src2[t + j * 256];
                    v.x += u.x; v.y += u.y; v.z += u.z; v.w += u.w;
                    dst[t + j * 256] = v;
                }
            }
            __syncthreads();
        }
        // prefetch A for step s+1 (independent of Bs)
        float4 nx[4];
        if (s < 31) {
            int off = ((s + 1) >> 4) * 64 + ((s + 1) & 15) * 4;
#pragma unroll
            for (int i = 0; i < 4; i++)
                nx[i] = *(const float4*)&A[(size_t)(r0 + i) * HID + off];
        }
        int h4 = s & 15;
#pragma unroll
        for (int u = 0; u < 4; u++) {
            ulonglong2 b01 = *(const ulonglong2*)&Bs[(h4 * 4 + u) * 128 + c0];
            ulonglong2 b23 = *(const ulonglong2*)&Bs[(h4 * 4 + u) * 128 + c0 + 4];
#pragma unroll
            for (int i = 0; i < 4; i++) {
                float a = (u == 0) ? av[i].x : (u == 1) ? av[i].y
                        : (u == 2) ? av[i].z : av[i].w;
                unsigned long long a2 = pack2(a);
                ffma2(acc2[i][0], a2, b01.x);
                ffma2(acc2[i][1], a2, b01.y);
                ffma2(acc2[i][2], a2, b23.x);
                ffma2(acc2[i][3], a2, b23.y);
            }
        }
        if (s < 31) {
#pragma unroll
            for (int i = 0; i < 4; i++) av[i] = nx[i];
        }
    }

    float accf[4][8];
#pragma unroll
    for (int i = 0; i < 4; i++)
#pragma unroll
        for (int p = 0; p < 4; p++) {
            float2 f = unpack2(acc2[i][p]);
            accf[i][2 * p] = f.x;
            accf[i][2 * p + 1] = f.y;
        }

    float4 bs0 = {0, 0, 0, 0}, bs1 = {0, 0, 0, 0};
    if (bias) {
        bs0 = *(const float4*)&bias[c0];
        bs1 = *(const float4*)&bias[c0 + 4];
    }
#pragma unroll
    for (int i = 0; i < 4; i++) {
        int m = r0 + i;
        if (m < M) {
            float4 w0, w1;
            w0.x = accf[i][0] + bs0.x; w0.y = accf[i][1] + bs0.y;
            w0.z = accf[i][2] + bs0.z; w0.w = accf[i][3] + bs0.w;
            w1.x = accf[i][4] + bs1.x; w1.y = accf[i][5] + bs1.y;
            w1.z = accf[i][6] + bs1.z; w1.w = accf[i][7] + bs1.w;
            *(float4*)&C[(size_t)m * HID + c0] = w0;
            *(float4*)&C[(size_t)m * HID + c0 + 4] = w1;
        }
    }

    if (atts) {
        float4 sa0 = *(const float4*)&atts[c0];
        float4 sa1 = *(const float4*)&atts[c0 + 4];
        float4 da0 = *(const float4*)&attd[c0];
        float4 da1 = *(const float4*)&attd[c0 + 4];
#pragma unroll
        for (int i = 0; i < 4; i++) {
            float ps = accf[i][0] * sa0.x + accf[i][1] * sa0.y + accf[i][2] * sa0.z + accf[i][3] * sa0.w
                     + accf[i][4] * sa1.x + accf[i][5] * sa1.y + accf[i][6] * sa1.z + accf[i][7] * sa1.w;
            float pd = accf[i][0] * da0.x + accf[i][1] * da0.y + accf[i][2] * da0.z + accf[i][3] * da0.w
                     + accf[i][4] * da1.x + accf[i][5] * da1.y + accf[i][6] * da1.z + accf[i][7] * da1.w;
            for (int o = 8; o; o >>= 1) {
                ps += __shfl_down_sync(0xffffffffu, ps, o, 16);
                pd += __shfl_down_sync(0xffffffffu, pd, o, 16);
            }
            int m = r0 + i;
            if (tc == 0 && m < M) { g_as[m] = ps; g_ad[m] = pd; }
        }
    }
}

// 32-row list-indirected GEMM: rows from g_list2 (0) / g_list3 (1)
// A-row prefetched one step ahead (g_nodes gather is the long-latency load)
__global__ void __launch_bounds__(256) k_gemml(int lsel, const float* __restrict__ Bm,
                                               const float* __restrict__ atts,
                                               const float* __restrict__ attd) {
    int cnt = lsel ? g_cnt3 : g_cnt2;
    if (blockIdx.x * 32 >= cnt) return;
    const int* list = lsel ? g_list3 : g_list2;

    int t = threadIdx.x;
    int rg = t >> 3, cg = t & 7;
    int m = blockIdx.x * 32 + rg;
    int k0 = cg * 16;

    bool ok = m < cnt;
    int row = ok ? list[m] : list[0];

    float acc[16];
#pragma unroll
    for (int j = 0; j < 16; j++) acc[j] = 0.f;

    float4 cur = *(const float4*)&g_nodes[(size_t)row * HID];
    for (int h = 0; h < HID; h += 4) {
        float4 nxt;
        if (h < HID - 4)
            nxt = *(const float4*)&g_nodes[(size_t)row * HID + h + 4];
        float a[4] = {cur.x, cur.y, cur.z, cur.w};
#pragma unroll
        for (int u = 0; u < 4; u++) {
            float br[16];
#pragma unroll
            for (int q = 0; q < 4; q++) {
                float4 w = *(const float4*)&Bm[(size_t)(h + u) * HID + k0 + q * 4];
                br[q * 4 + 0] = w.x; br[q * 4 + 1] = w.y;
                br[q * 4 + 2] = w.z; br[q * 4 + 3] = w.w;
            }
            float av = a[u];
#pragma unroll
            for (int j = 0; j < 16; j++) acc[j] += av * br[j];
        }
        if (h < HID - 4) cur = nxt;
    }

    if (ok) {
#pragma unroll
        for (int q = 0; q < 4; q++) {
            float4 w;
            w.x = acc[q * 4 + 0]; w.y = acc[q * 4 + 1];
            w.z = acc[q * 4 + 2]; w.w = acc[q * 4 + 3];
            *(float4*)&g_xl[(size_t)row * HID + k0 + q * 4] = w;
        }
    }

    float ps = 0.f, pd = 0.f;
#pragma unroll
    for (int q = 0; q < 4; q++) {
        float4 w = *(const float4*)&atts[k0 + q * 4];
        float4 u = *(const float4*)&attd[k0 + q * 4];
        ps += acc[q * 4 + 0] * w.x + acc[q * 4 + 1] * w.y + acc[q * 4 + 2] * w.z + acc[q * 4 + 3] * w.w;
        pd += acc[q * 4 + 0] * u.x + acc[q * 4 + 1] * u.y + acc[q * 4 + 2] * u.z + acc[q * 4 + 3] * u.w;
    }
    for (int o = 4; o; o >>= 1) {
        ps += __shfl_down_sync(0xffffffffu, ps, o, 8);
        pd += __shfl_down_sync(0xffffffffu, pd, o, 8);
    }
    if (cg == 0 && ok) { g_as[row] = ps; g_ad[row] = pd; }
}

// restricted softmax-aggregation: dst from list (0=list2, 1=list3, 2=ctx[+out])
__global__ void k_hopl(int lsel, const float* __restrict__ gbias,
                       float* __restrict__ out) {
    int wi = (blockIdx.x * blockDim.x + threadIdx.x) >> 5;
    int lane = threadIdx.x & 31;
    int cnt = (lsel == 0) ? g_cnt2 : (lsel == 1) ? g_cnt3 : Bq;
    if (wi >= cnt) return;
    int w = (lsel == 0) ? g_list2[wi] : (lsel == 1) ? g_list3[wi] : g_ctxn[wi];

    int s = g_off[w], e = g_off[w + 1];
    float adn = g_ad[w];
    float aself = g_as[w] + adn + g_loop[w];
    aself = aself >= 0.f ? aself : 0.2f * aself;
    float m = aself;
    for (int i = s + lane; i < e; i += 32) {
        float a = g_as[g_csrc[i]] + adn + g_cae[i];
        a = a >= 0.f ? a : 0.2f * a;
        m = fmaxf(m, a);
    }
    for (int o = 16; o; o >>= 1) m = fmaxf(m, __shfl_xor_sync(0xffffffffu, m, o));

    float eself = __expf(aself - m);
    float s_sum = eself;
    float4 v = ((const float4*)&g_xl[(size_t)w * HID])[lane];
    float4 acc;
    acc.x = eself * v.x; acc.y = eself * v.y; acc.z = eself * v.z; acc.w = eself * v.w;

    for (int i = s; i < e; i++) {
        int src = g_csrc[i];
        float a = g_as[src] + adn + g_cae[i];
        a = a >= 0.f ? a : 0.2f * a;
        float ee = __expf(a - m);
        s_sum += ee;
        float4 u = ((const float4*)&g_xl[(size_t)src * HID])[lane];
        acc.x += ee * u.x; acc.y += ee * u.y; acc.z += ee * u.z; acc.w += ee * u.w;
    }
    float inv = 1.f / s_sum;
    float4 bb = ((const float4*)gbias)[lane];
    float4 o;
    o.x = acc.x * inv + bb.x; o.y = acc.y * inv + bb.y;
    o.z = acc.z * inv + bb.z; o.w = acc.w * inv + bb.w;
    ((float4*)&g_nodes[(size_t)w * HID])[lane] = o;
    if (lsel == 2) ((float4*)&out[(size_t)wi * HID])[lane] = o;
}

extern "C" void kernel_launch(void* const* d_in, const int* in_sizes, int n_in,
                              void* d_out, int out_size) {
    const float* lm    = (const float*)d_in[0];
    const float* ne    = (const float*)d_in[1];
    const void*  ei    = d_in[2];
    const void*  et    = d_in[3];
    const void*  ctxn  = d_in[4];
    const float* Wlm  = (const float*)d_in[5];
    const float* blm  = (const float*)d_in[6];
    const float* Wbil = (const float*)d_in[7];
    const float* bbil = (const float*)d_in[8];
    const float* tab  = (const float*)d_in[9];
    const float* Wgat = (const float*)d_in[10];
    const float* atts = (const float*)d_in[11];
    const float* attd = (const float*)d_in[12];
    const float* Wed  = (const float*)d_in[13];
    const float* atte = (const float*)d_in[14];
    const float* gb   = (const float*)d_in[15];
    float* out = (float*)d_out;

    int E = in_sizes[2] / 2;
    int eb = (E + 255) / 256;
    int nb64 = (NN + 63) / 64;
    int nb32 = (NN + 31) / 32;
    int wb = (NN + 7) / 8;

    k_init<<<1024, 256>>>(ne);
    k_cvt<<<eb, 256>>>(ei, et, ctxn, E);
    k_prep<<<1, 128>>>(Wed, atte, tab);
    k_tmpp<<<dim3(HID, 2, 2), 128>>>(lm, Wbil);
    k_mark3<<<eb, 256>>>(E);
    k_scan<<<1, 1024>>>();
    k_mark2<<<eb, 256>>>(E);
    k_fill<<<eb, 256>>>(E);
    k_compact<<<(NN + 255) / 256, 256>>>();
    k_loopdot<<<wb, 256>>>();

    k_ctx<<<Bq, 1024>>>(lm, Wlm, blm);

    // nodes0: per-graph  xg @ (tmp partials summed)^T + b_bil
    dim3 g0((NPG + 63) / 64, Bq);
    k_gemmp<<<g0, 256>>>(0, nullptr, NPG, NPG * HID, bbil, nullptr, nullptr);

    // hop 1: full GEMM, aggregate at A2
    k_gemmp<<<dim3(nb64, 1), 256>>>(1, Wgat, NN, 0, nullptr, atts, attd);
    k_hopl<<<wb, 256>>>(0, gb, nullptr);

    // hop 2: GEMM over A2, aggregate at A3
    k_gemml<<<nb32, 256>>>(0, Wgat, atts, attd);
    k_hopl<<<wb, 256>>>(1, gb, nullptr);

    // hop 3: GEMM over A3, aggregate at ctx (+ output)
    k_gemml<<<nb32, 256>>>(1, Wgat, atts, attd);
    k_hopl<<<(Bq + 7) / 8, 256>>>(2, gb, out);
}

// round 13
// speedup vs baseline: 1.0656x; 1.0656x over previous
#include <cuda_runtime.h>

#define Bq   64
#define NPG  501
#define NN   (Bq * NPG)        // 32064
#define HID  128
#define LMD  1024
#define NREL 42
#define EMAX 520001
#define NPAD (NN + 128)

// ---------------- packed f32x2 helpers (Blackwell FFMA2) ----------------
__device__ __forceinline__ void ffma2(unsigned long long& acc,
                                      unsigned long long a, unsigned long long b) {
    asm("fma.rn.f32x2 %0, %1, %2, %0;" : "+l"(acc) : "l"(a), "l"(b));
}
__device__ __forceinline__ unsigned long long pack2(float x) {
    unsigned long long r;
    asm("mov.b64 %0, {%1, %1};" : "=l"(r) : "f"(x));
    return r;
}
__device__ __forceinline__ float2 unpack2(unsigned long long v) {
    float2 f;
    asm("mov.b64 {%0, %1}, %2;" : "=f"(f.x), "=f"(f.y) : "l"(v));
    return f;
}

// ---------------- scratch (device globals; no allocs) ----------------
__device__ int   g_src[EMAX];
__device__ int   g_dst[EMAX];
__device__ int   g_etype[EMAX];
__device__ int   g_ctxn[Bq];
__device__ float g_ctx[Bq * HID];
__device__ float g_tdot[NREL];
__device__ float g_tmpT[Bq * HID * HID];      // [b][h][k]
__device__ float g_x[NPAD * HID];
__device__ float g_nodes[NPAD * HID];
__device__ float g_xl[NPAD * HID];
__device__ float g_as[NPAD];
__device__ float g_ad[NPAD];
__device__ float g_loop[NN];
__device__ int   g_deg[NN];
__device__ int   g_off[NN + 1];
__device__ int   g_pos[NN];
__device__ int   g_csrc[EMAX];
__device__ float g_cae[EMAX];
// active-set pruning
__device__ int   g_isctx[NN];
__device__ int   g_m3[NN];
__device__ int   g_m2[NN];
__device__ int   g_list2[NN];
__device__ int   g_list3[NN];
__device__ int   g_cnt2;
__device__ int   g_cnt3;

// init: copy node_emb -> g_x, zero flags, counters; block 0 also computes
// table_dot (v_edge = W_edge@att_edge; tdot[r] = edge_table[r]·v_edge)
__global__ void k_init(const float* __restrict__ ne,
                       const float* __restrict__ We, const float* __restrict__ ae,
                       const float* __restrict__ tab) {
    __shared__ float sv[HID];
    int i = blockIdx.x * blockDim.x + threadIdx.x;
    int stride = gridDim.x * blockDim.x;
    if (blockIdx.x == 0) {
        int t = threadIdx.x;
        if (t < HID) {
            float acc = 0.f;
            for (int j = 0; j < HID; j++) acc += We[t * HID + j] * ae[j];
            sv[t] = acc;
        }
        __syncthreads();
        if (t < NREL) {
            float a2 = 0.f;
            for (int j = 0; j < HID; j++) a2 += tab[t * HID + j] * sv[j];
            g_tdot[t] = a2;
        }
    }
    const float4* s4 = (const float4*)ne;
    float4* d4 = (float4*)g_x;
    for (int j = i; j < NN * HID / 4; j += stride) d4[j] = s4[j];
    for (int j = i; j < NN; j += stride) {
        g_deg[j] = 0; g_isctx[j] = 0; g_m3[j] = 0; g_m2[j] = 0;
    }
    if (i == 0) { g_cnt2 = 0; g_cnt3 = 0; }
}

// cvt (dtype-flexible) + degree atomics + ctx marks, all in one pass
__global__ void k_cvt(const void* __restrict__ ei, const void* __restrict__ et,
                      const void* __restrict__ ctxn, int E) {
    int i = blockIdx.x * blockDim.x + threadIdx.x;
    bool is64 = (((const int*)ctxn)[1] == 0);
    if (i < E) {
        int s, d, t;
        if (is64) {
            s = (int)((const long long*)ei)[i];
            d = (int)((const long long*)ei)[E + i];
            t = (int)((const long long*)et)[i];
        } else {
            s = ((const int*)ei)[i];
            d = ((const int*)ei)[E + i];
            t = ((const int*)et)[i];
        }
        g_src[i] = s; g_dst[i] = d; g_etype[i] = t;
        atomicAdd(&g_deg[d], 1);
    }
    if (i < Bq) {
        int n = is64 ? (int)((const long long*)ctxn)[i] : ((const int*)ctxn)[i];
        g_ctxn[i] = n;
        g_isctx[n] = 1;
        g_m3[n] = 1;
    }
}

// tmpT[b][h][k] = sum_l lm[b,l]*W_bil[k,l,h] — round-9 proven version
// grid (128 k, 2 h-halves). Double-buffered smem pipeline.
__global__ void __launch_bounds__(256) k_tmpp(const float* __restrict__ lm,
                                              const float* __restrict__ Wb) {
    __shared__ float sW[2][32 * 64];
    __shared__ float sA[2][64 * 36];
    const int k = blockIdx.x;
    const int h0 = blockIdx.y * 64;
    const int t = threadIdx.x;
    const int tc = t & 7, tr = t >> 3;
    const int b0 = tr * 2;
    const int hw = tc * 4;
    const float* Wk = Wb + (size_t)k * LMD * HID;

    const int wl = t >> 3;
    const int wq = (t & 7) * 8;
    const int ab = t >> 2;
    const int al = (t & 3) * 8;

    unsigned long long acc[2][4];
#pragma unroll
    for (int i = 0; i < 2; i++)
#pragma unroll
        for (int p = 0; p < 4; p++) acc[i][p] = 0ull;

    float4 pw0 = *(const float4*)&Wk[(size_t)wl * HID + h0 + wq];
    float4 pw1 = *(const float4*)&Wk[(size_t)wl * HID + h0 + wq + 4];
    float4 pa0 = *(const float4*)&lm[(size_t)ab * LMD + al];
    float4 pa1 = *(const float4*)&lm[(size_t)ab * LMD + al + 4];
    *(float4*)&sW[0][wl * 64 + wq] = pw0;
    *(float4*)&sW[0][wl * 64 + wq + 4] = pw1;
    *(float4*)&sA[0][ab * 36 + al] = pa0;
    *(float4*)&sA[0][ab * 36 + al + 4] = pa1;
    __syncthreads();

    for (int c = 0; c < 32; c++) {
        if (c < 31) {
            int l0 = (c + 1) * 32;
            pw0 = *(const float4*)&Wk[(size_t)(l0 + wl) * HID + h0 + wq];
            pw1 = *(const float4*)&Wk[(size_t)(l0 + wl) * HID + h0 + wq + 4];
            pa0 = *(const float4*)&lm[(size_t)ab * LMD + l0 + al];
            pa1 = *(const float4*)&lm[(size_t)ab * LMD + l0 + al + 4];
        }
        const float* cW = sW[c & 1];
        const float* cA = sA[c & 1];
#pragma unroll
        for (int l = 0; l < 32; l += 2) {
            float2 a0 = *(const float2*)&cA[b0 * 36 + l];
            float2 a1 = *(const float2*)&cA[(b0 + 1) * 36 + l];
            ulonglong2 w0a = *(const ulonglong2*)&cW[l * 64 + hw];
            ulonglong2 w0b = *(const ulonglong2*)&cW[l * 64 + 32 + hw];
            ulonglong2 w1a = *(const ulonglong2*)&cW[(l + 1) * 64 + hw];
            ulonglong2 w1b = *(const ulonglong2*)&cW[(l + 1) * 64 + 32 + hw];
            unsigned long long p;
            p = pack2(a0.x);
            ffma2(acc[0][0], p, w0a.x); ffma2(acc[0][1], p, w0a.y);
            ffma2(acc[0][2], p, w0b.x); ffma2(acc[0][3], p, w0b.y);
            p = pack2(a1.x);
            ffma2(acc[1][0], p, w0a.x); ffma2(acc[1][1], p, w0a.y);
            ffma2(acc[1][2], p, w0b.x); ffma2(acc[1][3], p, w0b.y);
            p = pack2(a0.y);
            ffma2(acc[0][0], p, w1a.x); ffma2(acc[0][1], p, w1a.y);
            ffma2(acc[0][2], p, w1b.x); ffma2(acc[0][3], p, w1b.y);
            p = pack2(a1.y);
            ffma2(acc[1][0], p, w1a.x); ffma2(acc[1][1], p, w1a.y);
            ffma2(acc[1][2], p, w1b.x); ffma2(acc[1][3], p, w1b.y);
        }
        __syncthreads();
        if (c < 31) {
            int nb = (c + 1) & 1;
            *(float4*)&sW[nb][wl * 64 + wq] = pw0;
            *(float4*)&sW[nb][wl * 64 + wq + 4] = pw1;
            *(float4*)&sA[nb][ab * 36 + al] = pa0;
            *(float4*)&sA[nb][ab * 36 + al + 4] = pa1;
        }
        __syncthreads();
    }

#pragma unroll
    for (int i = 0; i < 2; i++) {
        size_t bb = (size_t)(b0 + i) * HID * HID + k;
#pragma unroll
        for (int p = 0; p < 4; p++) {
            float2 f = unpack2(acc[i][p]);
            int h = (p < 2) ? (h0 + hw + 2 * p) : (h0 + 32 + hw + 2 * (p - 2));
            g_tmpT[bb + (size_t)h * HID] = f.x;
            g_tmpT[bb + (size_t)(h + 1) * HID] = f.y;
        }
    }
}

__global__ void k_mark3(int E) {
    int i = blockIdx.x * blockDim.x + threadIdx.x;
    if (i < E && g_isctx[g_dst[i]]) g_m3[g_src[i]] = 1;
}

// single-block exclusive scan over g_deg -> g_off, g_pos
__global__ void k_scan() {
    __shared__ int sp[1024];
    int t = threadIdx.x;
    int base = t * 32;
    int loc[32];
    int s = 0;
#pragma unroll
    for (int i = 0; i < 32; i++) {
        int idx = base + i;
        int v = (idx < NN) ? g_deg[idx] : 0;
        loc[i] = s;
        s += v;
    }
    sp[t] = s;
    __syncthreads();
    for (int d = 1; d < 1024; d <<= 1) {
        int v = (t >= d) ? sp[t - d] : 0;
        __syncthreads();
        sp[t] += v;
        __syncthreads();
    }
    int chunk = (t == 0) ? 0 : sp[t - 1];
#pragma unroll
    for (int i = 0; i < 32; i++) {
        int idx = base + i;
        if (idx < NN) {
            int o = chunk + loc[i];
            g_off[idx] = o;
            g_pos[idx] = o;
        }
    }
    if (t == 1023) g_off[NN] = sp[1023];
}

// fused: mark2 (src of edges into m3 nodes) + CSR fill
__global__ void k_m2fill(int E) {
    int i = blockIdx.x * blockDim.x + threadIdx.x;
    if (i < E) {
        int d = g_dst[i];
        int s = g_src[i];
        if (g_m3[d]) g_m2[s] = 1;
        int p = atomicAdd(&g_pos[d], 1);
        g_csrc[p] = s;
        g_cae[p] = g_tdot[g_etype[i]];
    }
}

// fused: compact active lists + self-loop means
__global__ void k_cmploop() {
    int id = blockIdx.x * blockDim.x + threadIdx.x;
    if (id < NN) {
        int in3 = g_m3[id];
        int in2 = g_m2[id] | in3;
        if (in3) g_list3[atomicAdd(&g_cnt3, 1)] = id;
        if (in2) g_list2[atomicAdd(&g_cnt2, 1)] = id;
    }
    int w = id >> 5;
    int lane = id & 31;
    if (w < NN) {
        int s = g_off[w], e = g_off[w + 1];
        float acc = 0.f;
        for (int i = s + lane; i < e; i += 32) acc += g_cae[i];
        for (int o = 16; o; o >>= 1) acc += __shfl_xor_sync(0xffffffffu, acc, o);
        if (lane == 0) {
            int d = e - s;
            g_loop[w] = d ? acc / (float)d : 0.f;
        }
    }
}

// ctx_emb = lm @ W_lm + b_lm ; writes g_ctx and ctx rows of g_x
__global__ void __launch_bounds__(1024) k_ctx(const float* __restrict__ lm,
                                              const float* __restrict__ W,
                                              const float* __restrict__ bl) {
    __shared__ float red[1024];
    int b = blockIdx.x, t = threadIdx.x;
    int c = t & 127, lg = t >> 7;
    const float* l0 = lm + (size_t)b * LMD + lg * 128;
    const float* Wp = W + (size_t)(lg * 128) * HID + c;
    float a0 = 0.f, a1 = 0.f;
#pragma unroll 8
    for (int l = 0; l < 128; l += 2) {
        a0 += l0[l] * Wp[(size_t)l * HID];
        a1 += l0[l + 1] * Wp[(size_t)(l + 1) * HID];
    }
    red[t] = a0 + a1;
    __syncthreads();
    for (int s = 512; s >= 128; s >>= 1) {
        if (t < s) red[t] += red[t + s];
        __syncthreads();
    }
    if (t < 128) {
        float v = red[t] + bl[t];
        g_ctx[b * HID + t] = v;
        g_x[(size_t)g_ctxn[b] * HID + t] = v;
    }
}

// ===== FUSED nodes0 + hop-1 GEMM =====
// per 64-row tile of graph b:
//   C1 = x_tile @ tmp[b]^T + b_bil   (kept in smem; g_nodes never materialized)
//   xl = C1 @ W_gat ; a_src/a_dst row dots
__global__ void __launch_bounds__(256) k_fused(const float* __restrict__ bbil,
                                               const float* __restrict__ Wgat,
                                               const float* __restrict__ atts,
                                               const float* __restrict__ attd) {
    __shared__ float Bs[32 * 128];      // 16 KB staging (32 K-rows x 128 cols)
    __shared__ float C1s[64 * 128];     // 32 KB intermediate tile
    const int b = blockIdx.y;
    const int t = threadIdx.x;
    const int tc = t & 15, tr = t >> 4;
    const int rl = blockIdx.x * 64 + tr * 4;     // local row base within graph
    const int c0 = tc * 8;
    const float* A = g_x + (size_t)b * NPG * HID;
    const float* T = g_tmpT + (size_t)b * HID * HID;

    unsigned long long acc2[4][4];
#pragma unroll
    for (int i = 0; i < 4; i++)
#pragma unroll
        for (int p = 0; p < 4; p++) acc2[i][p] = 0ull;

    // ---- GEMM1: C1 = A @ T (T rows = h, cols = k) ----
#pragma unroll
    for (int ch = 0; ch < 4; ch++) {
        {
            const float4* src = (const float4*)(T + ch * 32 * HID);
            float4* dst = (float4*)Bs;
#pragma unroll
            for (int j = 0; j < 4; j++) dst[t + j * 256] = src[t + j * 256];
        }
        __syncthreads();
#pragma unroll
        for (int h4 = 0; h4 < 8; h4++) {
            int h = ch * 32 + h4 * 4;
            float4 av[4];
#pragma unroll
            for (int i = 0; i < 4; i++)
                av[i] = *(const float4*)&A[(size_t)(rl + i) * HID + h];
#pragma unroll
            for (int u = 0; u < 4; u++) {
                ulonglong2 b01 = *(const ulonglong2*)&Bs[(h4 * 4 + u) * 128 + c0];
                ulonglong2 b23 = *(const ulonglong2*)&Bs[(h4 * 4 + u) * 128 + c0 + 4];
#pragma unroll
                for (int i = 0; i < 4; i++) {
                    float a = (u == 0) ? av[i].x : (u == 1) ? av[i].y
                            : (u == 2) ? av[i].z : av[i].w;
                    unsigned long long a2 = pack2(a);
                    ffma2(acc2[i][0], a2, b01.x);
                    ffma2(acc2[i][1], a2, b01.y);
                    ffma2(acc2[i][2], a2, b23.x);
                    ffma2(acc2[i][3], a2, b23.y);
                }
            }
        }
        __syncthreads();
    }

    // bias + write C1 tile to smem (tile-local row = tr*4+i)
    {
        float4 bs0 = *(const float4*)&bbil[c0];
        float4 bs1 = *(const float4*)&bbil[c0 + 4];
#pragma unroll
        for (int i = 0; i < 4; i++) {
            float2 f0 = unpack2(acc2[i][0]);
            float2 f1 = unpack2(acc2[i][1]);
            float2 f2 = unpack2(acc2[i][2]);
            float2 f3 = unpack2(acc2[i][3]);
            float4 w0, w1;
            w0.x = f0.x + bs0.x; w0.y = f0.y + bs0.y;
            w0.z = f1.x + bs0.z; w0.w = f1.y + bs0.w;
            w1.x = f2.x + bs1.x; w1.y = f2.y + bs1.y;
            w1.z = f3.x + bs1.z; w1.w = f3.y + bs1.w;
            *(float4*)&C1s[(tr * 4 + i) * 128 + c0] = w0;
            *(float4*)&C1s[(tr * 4 + i) * 128 + c0 + 4] = w1;
        }
    }
    __syncthreads();

    // ---- GEMM2: xl = C1 @ Wgat ----
#pragma unroll
    for (int i = 0; i < 4; i++)
#pragma unroll
        for (int p = 0; p < 4; p++) acc2[i][p] = 0ull;

#pragma unroll
    for (int ch = 0; ch < 4; ch++) {
        {
            const float4* src = (const float4*)(Wgat + ch * 32 * HID);
            float4* dst = (float4*)Bs;
#pragma unroll
            for (int j = 0; j < 4; j++) dst[t + j * 256] = src[t + j * 256];
        }
        __syncthreads();
#pragma unroll
        for (int h4 = 0; h4 < 8; h4++) {
            float4 av[4];
#pragma unroll
            for (int i = 0; i < 4; i++)
                av[i] = *(const float4*)&C1s[(tr * 4 + i) * 128 + ch * 32 + h4 * 4];
#pragma unroll
            for (int u = 0; u < 4; u++) {
                ulonglong2 b01 = *(const ulonglong2*)&Bs[(h4 * 4 + u) * 128 + c0];
                ulonglong2 b23 = *(const ulonglong2*)&Bs[(h4 * 4 + u) * 128 + c0 + 4];
#pragma unroll
                for (int i = 0; i < 4; i++) {
                    float a = (u == 0) ? av[i].x : (u == 1) ? av[i].y
                            : (u == 2) ? av[i].z : av[i].w;
                    unsigned long long a2 = pack2(a);
                    ffma2(acc2[i][0], a2, b01.x);
                    ffma2(acc2[i][1], a2, b01.y);
                    ffma2(acc2[i][2], a2, b23.x);
                    ffma2(acc2[i][3], a2, b23.y);
                }
            }
        }
        __syncthreads();
    }

    float accf[4][8];
#pragma unroll
    for (int i = 0; i < 4; i++)
#pragma unroll
        for (int p = 0; p < 4; p++) {
            float2 f = unpack2(acc2[i][p]);
            accf[i][2 * p] = f.x;
            accf[i][2 * p + 1] = f.y;
        }

#pragma unroll
    for (int i = 0; i < 4; i++) {
        if (rl + i < NPG) {
            size_t m = (size_t)b * NPG + rl + i;
            float4 w0, w1;
            w0.x = accf[i][0]; w0.y = accf[i][1];
            w0.z = accf[i][2]; w0.w = accf[i][3];
            w1.x = accf[i][4]; w1.y = accf[i][5];
            w1.z = accf[i][6]; w1.w = accf[i][7];
            *(float4*)&g_xl[m * HID + c0] = w0;
            *(float4*)&g_xl[m * HID + c0 + 4] = w1;
        }
    }

    {
        float4 sa0 = *(const float4*)&atts[c0];
        float4 sa1 = *(const float4*)&atts[c0 + 4];
        float4 da0 = *(const float4*)&attd[c0];
        float4 da1 = *(const float4*)&attd[c0 + 4];
#pragma unroll
        for (int i = 0; i < 4; i++) {
            float ps = accf[i][0] * sa0.x + accf[i][1] * sa0.y + accf[i][2] * sa0.z + accf[i][3] * sa0.w
                     + accf[i][4] * sa1.x + accf[i][5] * sa1.y + accf[i][6] * sa1.z + accf[i][7] * sa1.w;
            float pd = accf[i][0] * da0.x + accf[i][1] * da0.y + accf[i][2] * da0.z + accf[i][3] * da0.w
                     + accf[i][4] * da1.x + accf[i][5] * da1.y + accf[i][6] * da1.z + accf[i][7] * da1.w;
            for (int o = 8; o; o >>= 1) {
                ps += __shfl_down_sync(0xffffffffu, ps, o, 16);
                pd += __shfl_down_sync(0xffffffffu, pd, o, 16);
            }
            if (tc == 0 && rl + i < NPG) {
                size_t m = (size_t)b * NPG + rl + i;
                g_as[m] = ps;
                g_ad[m] = pd;
            }
        }
    }
}

// 32-row list-indirected GEMM: rows from g_list2 (0) / g_list3 (1)
__global__ void __launch_bounds__(256) k_gemml(int lsel, const float* __restrict__ Bm,
                                               const float* __restrict__ atts,
                                               const float* __restrict__ attd) {
    int cnt = lsel ? g_cnt3 : g_cnt2;
    if (blockIdx.x * 32 >= cnt) return;
    const int* list = lsel ? g_list3 : g_list2;

    int t = threadIdx.x;
    int rg = t >> 3, cg = t & 7;
    int m = blockIdx.x * 32 + rg;
    int k0 = cg * 16;

    bool ok = m < cnt;
    int row = ok ? list[m] : list[0];

    float acc[16];
#pragma unroll
    for (int j = 0; j < 16; j++) acc[j] = 0.f;

    for (int h = 0; h < HID; h += 4) {
        float4 v = *(const float4*)&g_nodes[(size_t)row * HID + h];
        float a[4] = {v.x, v.y, v.z, v.w};
#pragma unroll
        for (int u = 0; u < 4; u++) {
            float br[16];
#pragma unroll
            for (int q = 0; q < 4; q++) {
                float4 w = *(const float4*)&Bm[(size_t)(h + u) * HID + k0 + q * 4];
                br[q * 4 + 0] = w.x; br[q * 4 + 1] = w.y;
                br[q * 4 + 2] = w.z; br[q * 4 + 3] = w.w;
            }
            float av = a[u];
#pragma unroll
            for (int j = 0; j < 16; j++) acc[j] += av * br[j];
        }
    }

    if (ok) {
#pragma unroll
        for (int q = 0; q < 4; q++) {
            float4 w;
            w.x = acc[q * 4 + 0]; w.y = acc[q * 4 + 1];
            w.z = acc[q * 4 + 2]; w.w = acc[q * 4 + 3];
            *(float4*)&g_xl[(size_t)row * HID + k0 + q * 4] = w;
        }
    }

    float ps = 0.f, pd = 0.f;
#pragma unroll
    for (int q = 0; q < 4; q++) {
        float4 w = *(const float4*)&atts[k0 + q * 4];
        float4 u = *(const float4*)&attd[k0 + q * 4];
        ps += acc[q * 4 + 0] * w.x + acc[q * 4 + 1] * w.y + acc[q * 4 + 2] * w.z + acc[q * 4 + 3] * w.w;
        pd += acc[q * 4 + 0] * u.x + acc[q * 4 + 1] * u.y + acc[q * 4 + 2] * u.z + acc[q * 4 + 3] * u.w;
    }
    for (int o = 4; o; o >>= 1) {
        ps += __shfl_down_sync(0xffffffffu, ps, o, 8);
        pd += __shfl_down_sync(0xffffffffu, pd, o, 8);
    }
    if (cg == 0 && ok) { g_as[row] = ps; g_ad[row] = pd; }
}

// restricted softmax-aggregation: dst from list (0=list2, 1=list3, 2=ctx[+out])
__global__ void k_hopl(int lsel, const float* __restrict__ gbias,
                       float* __restrict__ out) {
    int wi = (blockIdx.x * blockDim.x + threadIdx.x) >> 5;
    int lane = threadIdx.x & 31;
    int cnt = (lsel == 0) ? g_cnt2 : (lsel == 1) ? g_cnt3 : Bq;
    if (wi >= cnt) return;
    int w = (lsel == 0) ? g_list2[wi] : (lsel == 1) ? g_list3[wi] : g_ctxn[wi];

    int s = g_off[w], e = g_off[w + 1];
    float adn = g_ad[w];
    float aself = g_as[w] + adn + g_loop[w];
    aself = aself >= 0.f ? aself : 0.2f * aself;
    float m = aself;
    for (int i = s + lane; i < e; i += 32) {
        float a = g_as[g_csrc[i]] + adn + g_cae[i];
        a = a >= 0.f ? a : 0.2f * a;
        m = fmaxf(m, a);
    }
    for (int o = 16; o; o >>= 1) m = fmaxf(m, __shfl_xor_sync(0xffffffffu, m, o));

    float eself = __expf(aself - m);
    float s_sum = eself;
    float4 v = ((const float4*)&g_xl[(size_t)w * HID])[lane];
    float4 acc;
    acc.x = eself * v.x; acc.y = eself * v.y; acc.z = eself * v.z; acc.w = eself * v.w;

    for (int i = s; i < e; i++) {
        int src = g_csrc[i];
        float a = g_as[src] + adn + g_cae[i];
        a = a >= 0.f ? a : 0.2f * a;
        float ee = __expf(a - m);
        s_sum += ee;
        float4 u = ((const float4*)&g_xl[(size_t)src * HID])[lane];
        acc.x += ee * u.x; acc.y += ee * u.y; acc.z += ee * u.z; acc.w += ee * u.w;
    }
    float inv = 1.f / s_sum;
    float4 bb = ((const float4*)gbias)[lane];
    float4 o;
    o.x = acc.x * inv + bb.x; o.y = acc.y * inv + bb.y;
    o.z = acc.z * inv + bb.z; o.w = acc.w * inv + bb.w;
    ((float4*)&g_nodes[(size_t)w * HID])[lane] = o;
    if (lsel == 2) ((float4*)&out[(size_t)wi * HID])[lane] = o;
}

extern "C" void kernel_launch(void* const* d_in, const int* in_sizes, int n_in,
                              void* d_out, int out_size) {
    const float* lm    = (const float*)d_in[0];
    const float* ne    = (const float*)d_in[1];
    const void*  ei    = d_in[2];
    const void*  et    = d_in[3];
    const void*  ctxn  = d_in[4];
    const float* Wlm  = (const float*)d_in[5];
    const float* blm  = (const float*)d_in[6];
    const float* Wbil = (const float*)d_in[7];
    const float* bbil = (const float*)d_in[8];
    const float* tab  = (const float*)d_in[9];
    const float* Wgat = (const float*)d_in[10];
    const float* atts = (const float*)d_in[11];
    const float* attd = (const float*)d_in[12];
    const float* Wed  = (const float*)d_in[13];
    const float* atte = (const float*)d_in[14];
    const float* gb   = (const float*)d_in[15];
    float* out = (float*)d_out;

    int E = in_sizes[2] / 2;
    int eb = (E + 255) / 256;
    int nb32 = (NN + 31) / 32;
    int wb = (NN + 7) / 8;

    k_init<<<1024, 256>>>(ne, Wed, atte, tab);
    k_cvt<<<eb, 256>>>(ei, et, ctxn, E);
    k_tmpp<<<dim3(HID, 2), 256>>>(lm, Wbil);
    k_mark3<<<eb, 256>>>(E);
    k_scan<<<1, 1024>>>();
    k_m2fill<<<eb, 256>>>(E);
    k_cmploop<<<wb, 256>>>();
    k_ctx<<<Bq, 1024>>>(lm, Wlm, blm);

    // fused nodes0 + hop-1 GEMM (writes g_xl, g_as, g_ad only)
    dim3 gf((NPG + 63) / 64, Bq);
    k_fused<<<gf, 256>>>(bbil, Wgat, atts, attd);
    k_hopl<<<wb, 256>>>(0, gb, nullptr);

    // hop 2: GEMM over A2, aggregate at A3
    k_gemml<<<nb32, 256>>>(0, Wgat, atts, attd);
    k_hopl<<<wb, 256>>>(1, gb, nullptr);

    // hop 3: GEMM over A3, aggregate at ctx (+ output)
    k_gemml<<<nb32, 256>>>(1, Wgat, atts, attd);
    k_hopl<<<(Bq + 7) / 8, 256>>>(2, gb, out);
}